// round 5
// baseline (speedup 1.0000x reference)
#include <cuda_runtime.h>

// Round 5: dual-pipe fp32 (FFMA2 + scalar FFMA concurrently) in both kernels,
// plus a shuffle-based epilogue (no gates smem, one barrier/step, h double-buffered).

#define BB 256
#define SS 2048
#define II 64
#define HH 128
#define GG 512
#define NCTA 128
#define NTHR 256

// scan weight split (k = 128 recurrent rows)
#define PK   64          // packed-FFMA2 rows (register, pair-packed)
#define SRK  16          // scalar rows in registers
#define SMKR 48          // scalar rows in smem

// GEMM tiling
#define GM_M 256
#define GM_N 64
#define AS_STRIDE 65
#define BD_STRIDE 160
#define GEMM_SMEM_FLOATS (GM_M * AS_STRIDE + II * BD_STRIDE)
#define GEMM_SMEM_BYTES  (GEMM_SMEM_FLOATS * 4)

// scan smem: sws[SMKR][256] float2 + h double buffer 2x2x128
#define SWS_F2   (SMKR * 256)
#define SCAN_SMEM_BYTES (SWS_F2 * 8 + 2 * 2 * HH * 4)

typedef unsigned long long u64;

__device__ float g_pre[(long long)BB * SS * GG];   // 1 GB scratch

__device__ __forceinline__ u64 ffma2(u64 a, u64 b, u64 c) {
    u64 d;
    asm("fma.rn.f32x2 %0, %1, %2, %3;" : "=l"(d) : "l"(a), "l"(b), "l"(c));
    return d;
}
__device__ __forceinline__ u64 packf2(float lo, float hi) {
    u64 r;
    asm("mov.b64 %0, {%1, %2};" : "=l"(r) : "f"(lo), "f"(hi));
    return r;
}
__device__ __forceinline__ float2 unpackf2(u64 v) {
    float2 r;
    asm("mov.b64 {%0, %1}, %2;" : "=f"(r.x), "=f"(r.y) : "l"(v));
    return r;
}
__device__ __forceinline__ float fast_tanh(float x) {
    float xc = fminf(fmaxf(x, -12.0f), 12.0f);
    float e  = __expf(2.0f * xc);
    return __fdividef(e - 1.0f, e + 1.0f);
}

// ---------------------------------------------------------------------------
// Kernel 1: pre = x @ W^T + b   (dual-pipe: n 0..3 packed over m-pairs, n 4..7 scalar)
// ---------------------------------------------------------------------------
__global__ void __launch_bounds__(256, 2)
pre_gemm_kernel(const float* __restrict__ xg, const float* __restrict__ Wm,
                const float* __restrict__ bias, float* __restrict__ pre)
{
    extern __shared__ float sm[];
    float* As = sm;                      // [GM_M][AS_STRIDE]
    float* Bd = sm + GM_M * AS_STRIDE;   // [II][BD_STRIDE] duplicated pairs

    const int tid   = threadIdx.x;
    const int mbase = blockIdx.x * GM_M;
    const int nbase = blockIdx.y * GM_N;

#pragma unroll
    for (int t = 0; t < 16; t++) {
        int idx = tid + t * 256;
        int row = idx >> 4, kq = idx & 15;
        float4 v = *(const float4*)(xg + (long long)(mbase + row) * II + kq * 4);
        float* p = As + row * AS_STRIDE + kq * 4;
        p[0] = v.x; p[1] = v.y; p[2] = v.z; p[3] = v.w;
    }
#pragma unroll
    for (int t = 0; t < 4; t++) {
        int idx = tid + t * 256;
        int g = idx >> 4, kq = idx & 15;
        float4 v = *(const float4*)(Wm + (long long)(nbase + g) * II + kq * 4);
        int grp = g >> 3, win = g & 7;
        float vv[4] = {v.x, v.y, v.z, v.w};
#pragma unroll
        for (int j = 0; j < 4; j++) {
            float* p = Bd + (4 * kq + j) * BD_STRIDE + grp * 20 + win * 2;
            p[0] = vv[j]; p[1] = vv[j];
        }
    }
    __syncthreads();

    const int tx = tid & 7;
    const int ty = tid >> 3;
    const float* aB = As + ty * 8 * AS_STRIDE;
    const float* bB = Bd + tx * 20;

    u64   acc_p[4][4];
    float acc_s[8][4];
#pragma unroll
    for (int i = 0; i < 4; i++)
#pragma unroll
        for (int n = 0; n < 4; n++) acc_p[i][n] = 0;
#pragma unroll
    for (int i = 0; i < 8; i++)
#pragma unroll
        for (int n = 0; n < 4; n++) acc_s[i][n] = 0.0f;

#pragma unroll 4
    for (int k = 0; k < II; k++) {
        const float* bk = bB + k * BD_STRIDE;
        ulonglong2 bp  = *(const ulonglong2*)(bk);       // (b0,b0)(b1,b1)
        ulonglong2 bp2 = *(const ulonglong2*)(bk + 4);   // (b2,b2)(b3,b3)
        float4 bs1 = *(const float4*)(bk + 8);           // b4 b4 b5 b5
        float4 bs2 = *(const float4*)(bk + 12);          // b6 b6 b7 b7

        float a[8];
#pragma unroll
        for (int i = 0; i < 8; i++) a[i] = aB[i * AS_STRIDE + k];
        u64 ap[4];
#pragma unroll
        for (int mp = 0; mp < 4; mp++) ap[mp] = packf2(a[2 * mp], a[2 * mp + 1]);

#pragma unroll
        for (int mp = 0; mp < 4; mp++) {
            acc_p[mp][0] = ffma2(ap[mp], bp.x,  acc_p[mp][0]);
            acc_p[mp][1] = ffma2(ap[mp], bp.y,  acc_p[mp][1]);
            acc_p[mp][2] = ffma2(ap[mp], bp2.x, acc_p[mp][2]);
            acc_p[mp][3] = ffma2(ap[mp], bp2.y, acc_p[mp][3]);
        }
#pragma unroll
        for (int mi = 0; mi < 8; mi++) {
            acc_s[mi][0] = fmaf(a[mi], bs1.x, acc_s[mi][0]);
            acc_s[mi][1] = fmaf(a[mi], bs1.z, acc_s[mi][1]);
            acc_s[mi][2] = fmaf(a[mi], bs2.x, acc_s[mi][2]);
            acc_s[mi][3] = fmaf(a[mi], bs2.z, acc_s[mi][3]);
        }
    }

    float bl[8];
#pragma unroll
    for (int n = 0; n < 8; n++) bl[n] = bias[nbase + tx * 8 + n];

#pragma unroll
    for (int mi = 0; mi < 8; mi++) {
        float v[8];
#pragma unroll
        for (int n = 0; n < 4; n++) {
            float2 pv = unpackf2(acc_p[mi >> 1][n]);
            v[n] = (mi & 1) ? pv.y : pv.x;
        }
#pragma unroll
        for (int n = 0; n < 4; n++) v[4 + n] = acc_s[mi][n];
        long long r = (long long)(mbase + ty * 8 + mi) * GG + nbase + tx * 8;
        float4 lo = {v[0] + bl[0], v[1] + bl[1], v[2] + bl[2], v[3] + bl[3]};
        float4 hi = {v[4] + bl[4], v[5] + bl[5], v[6] + bl[6], v[7] + bl[7]};
        *(float4*)(pre + r)     = lo;
        *(float4*)(pre + r + 4) = hi;
    }
}

// ---------------------------------------------------------------------------
// Kernel 2: persistent scan, dual-pipe mainloop, shuffle epilogue, 1 barrier.
// Lane l of warp w owns gate columns c0 = 16l + 2w, c1 = c0 + 1.
// ---------------------------------------------------------------------------
__global__ void __launch_bounds__(NTHR, 1)
slstm_scan_kernel(const float* __restrict__ pre, const float* __restrict__ Rm,
                  float* __restrict__ out)
{
    extern __shared__ float smem[];
    float2* sws = (float2*)smem;                 // [SMKR][256] per-(w,l) col pairs
    float*  hb  = smem + SWS_F2 * 2;             // [2][2][HH] h double buffer

    const int tid = threadIdx.x;
    const int w   = tid >> 5;
    const int l   = tid & 31;
    const int c0  = 16 * l + 2 * w;
    const int c1  = c0 + 1;
    const int b0  = blockIdx.x * 2;

    // packed weights: rows [0, PK), pair-packed per column
    u64 wp0[PK / 2], wp1[PK / 2];
#pragma unroll
    for (int j = 0; j < PK / 2; j++) {
        wp0[j] = packf2(Rm[(2 * j) * GG + c0], Rm[(2 * j + 1) * GG + c0]);
        wp1[j] = packf2(Rm[(2 * j) * GG + c1], Rm[(2 * j + 1) * GG + c1]);
    }
    // scalar register weights: rows [PK, PK+SRK)
    float ws0[SRK], ws1[SRK];
#pragma unroll
    for (int j = 0; j < SRK; j++) {
        ws0[j] = Rm[(PK + j) * GG + c0];
        ws1[j] = Rm[(PK + j) * GG + c1];
    }
    // smem scalar weights: rows [PK+SRK, 128), stored as float2(c0,c1) per thread
    for (int j = 0; j < SMKR; j++) {
        int k = PK + SRK + j;
        sws[j * 256 + w * 32 + l] = make_float2(Rm[k * GG + c0], Rm[k * GG + c1]);
    }

    // zero h buffer 0 (and 1 for safety): 2*2*128 = 512 floats
    hb[tid] = 0.0f;
    hb[tid + 256] = 0.0f;
    __syncthreads();

    const float* pr0 = pre + (long long)(b0)     * SS * GG;
    const float* pr1 = pre + (long long)(b0 + 1) * SS * GG;

    float p00 = __ldg(pr0 + c0), p01 = __ldg(pr0 + c1);
    float p10 = __ldg(pr1 + c0), p11 = __ldg(pr1 + c1);

    // persistent state for this lane's (row, hid)
    const int my_row = (l >> 4) & 1;
    const int my_hid = 16 * (l & 7) + 2 * w + ((l >> 3) & 1);
    float c_ = 0.0f, n_ = 0.0f, m_ = 0.0f;

    const bool lo16 = (l < 16);
    const bool b3   = ((l >> 3) & 1) != 0;
    const float2* swsl = sws + w * 32 + l;

#pragma unroll 1
    for (int step = 0; step < SS; step++) {
        const float* h0 = hb + (step & 1) * 256;
        const float* h1 = h0 + HH;
        float* hn = hb + ((step + 1) & 1) * 256;

        // prefetch next pre
        float q00 = 0.f, q01 = 0.f, q10 = 0.f, q11 = 0.f;
        if (step + 1 < SS) {
            long long off = (long long)(step + 1) * GG;
            q00 = __ldg(pr0 + off + c0);
            q01 = __ldg(pr0 + off + c1);
            q10 = __ldg(pr1 + off + c0);
            q11 = __ldg(pr1 + off + c1);
        }

        u64 P00 = 0, P10 = 0, P01 = 0, P11 = 0;            // packed acc [col][row]
        float S00a = 0, S00b = 0, S10a = 0, S10b = 0;       // scalar acc
        float S01a = 0, S01b = 0, S11a = 0, S11b = 0;

#pragma unroll
        for (int i = 0; i < 16; i++) {
            // packed rows 4i..4i+3
            ulonglong2 hp0 = *(const ulonglong2*)(h0 + 4 * i);
            ulonglong2 hp1 = *(const ulonglong2*)(h1 + 4 * i);
            P00 = ffma2(hp0.x, wp0[2 * i],     P00);
            P10 = ffma2(hp0.x, wp1[2 * i],     P10);
            P01 = ffma2(hp1.x, wp0[2 * i],     P01);
            P11 = ffma2(hp1.x, wp1[2 * i],     P11);
            P00 = ffma2(hp0.y, wp0[2 * i + 1], P00);
            P10 = ffma2(hp0.y, wp1[2 * i + 1], P10);
            P01 = ffma2(hp1.y, wp0[2 * i + 1], P01);
            P11 = ffma2(hp1.y, wp1[2 * i + 1], P11);

            // scalar rows PK + 4i .. PK + 4i+3
            float4 q0 = *(const float4*)(h0 + PK + 4 * i);
            float4 q1 = *(const float4*)(h1 + PK + 4 * i);
            float wc0[4], wc1[4];
            if (i < SRK / 4) {
#pragma unroll
                for (int d = 0; d < 4; d++) { wc0[d] = ws0[4 * i + d]; wc1[d] = ws1[4 * i + d]; }
            } else {
#pragma unroll
                for (int d = 0; d < 4; d++) {
                    float2 wv = swsl[(4 * i - SRK + d) * 256];
                    wc0[d] = wv.x; wc1[d] = wv.y;
                }
            }
            S00a = fmaf(q0.x, wc0[0], S00a);  S10a = fmaf(q0.x, wc1[0], S10a);
            S01a = fmaf(q1.x, wc0[0], S01a);  S11a = fmaf(q1.x, wc1[0], S11a);
            S00b = fmaf(q0.y, wc0[1], S00b);  S10b = fmaf(q0.y, wc1[1], S10b);
            S01b = fmaf(q1.y, wc0[1], S01b);  S11b = fmaf(q1.y, wc1[1], S11b);
            S00a = fmaf(q0.z, wc0[2], S00a);  S10a = fmaf(q0.z, wc1[2], S10a);
            S01a = fmaf(q1.z, wc0[2], S01a);  S11a = fmaf(q1.z, wc1[2], S11a);
            S00b = fmaf(q0.w, wc0[3], S00b);  S10b = fmaf(q0.w, wc1[3], S10b);
            S01b = fmaf(q1.w, wc0[3], S01b);  S11b = fmaf(q1.w, wc1[3], S11b);
        }

        float2 t0 = unpackf2(P00), t1 = unpackf2(P10);
        float2 t2 = unpackf2(P01), t3 = unpackf2(P11);
        float aa = t0.x + t0.y + S00a + S00b + p00;   // g(r0, c0)
        float bb = t1.x + t1.y + S10a + S10b + p01;   // g(r0, c1)
        float cc = t2.x + t2.y + S01a + S01b + p10;   // g(r1, c0)
        float dd = t3.x + t3.y + S11a + S11b + p11;   // g(r1, c1)

        // ---- warp-local gate transpose: 4 bfly shuffles ----
        float u1 = lo16 ? cc : aa;
        float u2 = lo16 ? dd : bb;
        float r1v = __shfl_xor_sync(0xFFFFFFFFu, u1, 16);
        float r2v = __shfl_xor_sync(0xFFFFFFFFu, u2, 16);
        float A = lo16 ? aa : r1v;
        float B = lo16 ? bb : r2v;
        float C = lo16 ? r1v : cc;
        float D = lo16 ? r2v : dd;
        float s1in = b3 ? A : B;
        float s2in = b3 ? C : D;
        float e1 = __shfl_xor_sync(0xFFFFFFFFu, s1in, 8);
        float e2 = __shfl_xor_sync(0xFFFFFFFFu, s2in, 8);
        float iv = b3 ? e1 : A;
        float fv = b3 ? B  : e1;
        float ov = b3 ? e2 : C;
        float zv = b3 ? D  : e2;

        // ---- exponential-gating state update (this lane's (row, hid)) ----
        float tz = fast_tanh(zv);
        float so = __fdividef(1.0f, 1.0f + __expf(-ov));
        float lf = fminf(fv, 0.0f) - __logf(1.0f + __expf(-fabsf(fv)));
        float mn = fmaxf(lf + m_, iv);
        float ip = __expf(iv - mn);
        float fp = __expf(lf + m_ - mn);
        c_ = fp * c_ + ip * tz;
        n_ = fp * n_ + ip;
        m_ = mn;
        float hv = so * fast_tanh(__fdividef(c_, n_));

        hn[my_row * HH + my_hid] = hv;
        out[((long long)(b0 + my_row) * SS + step) * HH + my_hid] = hv;

        p00 = q00; p01 = q01; p10 = q10; p11 = q11;
        __syncthreads();
    }
}

extern "C" void kernel_launch(void* const* d_in, const int* in_sizes, int n_in,
                              void* d_out, int out_size)
{
    const float* xg = (const float*)d_in[0];
    const float* Wm = (const float*)d_in[1];
    const float* Rm = (const float*)d_in[2];
    const float* bv = (const float*)d_in[3];
    if (n_in >= 3 && in_sizes[1] == HH * GG && in_sizes[2] == GG * II) {
        const float* t = Wm; Wm = Rm; Rm = t;
    }
    float* out = (float*)d_out;

    float* pre = nullptr;
    cudaGetSymbolAddress((void**)&pre, g_pre);

    cudaFuncSetAttribute(pre_gemm_kernel,
                         cudaFuncAttributeMaxDynamicSharedMemorySize, GEMM_SMEM_BYTES);
    cudaFuncSetAttribute(slstm_scan_kernel,
                         cudaFuncAttributeMaxDynamicSharedMemorySize, SCAN_SMEM_BYTES);

    dim3 ggrid((BB * SS) / GM_M, GG / GM_N);
    pre_gemm_kernel<<<ggrid, 256, GEMM_SMEM_BYTES>>>(xg, Wm, bv, pre);
    slstm_scan_kernel<<<NCTA, NTHR, SCAN_SMEM_BYTES>>>(pre, Rm, out);
}

// round 7
// speedup vs baseline: 1.3115x; 1.3115x over previous
#include <cuda_runtime.h>
#include <cuda_bf16.h>
#include <cstdint>

// Round 7: HMMA (mma.sync bf16, sm_80 baseline PTX - compiles on compute_103)
// split-precision GEMM for pre = x@W^T, + scan = pure-FFMA2 mainloop with
// shuffle epilogue (1 barrier/step).

#define BB 256
#define SS 2048
#define II 64
#define HH 128
#define GG 512
#define NCTA 128
#define NTHR 256
#define REG_K 96
#define SMK   32
#define PTS  (SMK * 2 + 4)
#define SW_FLOATS (NTHR * PTS)
#define SCAN_SMEM_BYTES (SW_FLOATS * 4 + 2 * 2 * HH * 4)

typedef unsigned long long u64;

__device__ float g_pre[(long long)BB * SS * GG];                 // 1 GB scratch
__device__ __align__(16) unsigned g_wh[GG * II / 2];             // W hi bf16 pairs
__device__ __align__(16) unsigned g_wl[GG * II / 2];             // W lo residual

__device__ __forceinline__ u64 ffma2(u64 a, u64 b, u64 c) {
    u64 d;
    asm("fma.rn.f32x2 %0, %1, %2, %3;" : "=l"(d) : "l"(a), "l"(b), "l"(c));
    return d;
}
__device__ __forceinline__ u64 packf2(float lo, float hi) {
    u64 r;
    asm("mov.b64 %0, {%1, %2};" : "=l"(r) : "f"(lo), "f"(hi));
    return r;
}
__device__ __forceinline__ float2 unpackf2(u64 v) {
    float2 r;
    asm("mov.b64 {%0, %1}, %2;" : "=f"(r.x), "=f"(r.y) : "l"(v));
    return r;
}
__device__ __forceinline__ float fast_tanh(float x) {
    float xc = fminf(fmaxf(x, -12.0f), 12.0f);
    float e  = __expf(2.0f * xc);
    return __fdividef(e - 1.0f, e + 1.0f);
}
__device__ __forceinline__ unsigned pack_bf16_hi(float a, float b) {
    __nv_bfloat16 ah = __float2bfloat16(a), bh = __float2bfloat16(b);
    return (unsigned)__bfloat16_as_ushort(ah) | ((unsigned)__bfloat16_as_ushort(bh) << 16);
}
__device__ __forceinline__ unsigned pack_bf16_lo(float a, float b) {
    __nv_bfloat16 ah = __float2bfloat16(a), bh = __float2bfloat16(b);
    __nv_bfloat16 al = __float2bfloat16(a - __bfloat162float(ah));
    __nv_bfloat16 bl = __float2bfloat16(b - __bfloat162float(bh));
    return (unsigned)__bfloat16_as_ushort(al) | ((unsigned)__bfloat16_as_ushort(bl) << 16);
}
__device__ __forceinline__ void mma16816(float* c, const unsigned* a,
                                         unsigned b0, unsigned b1) {
    asm volatile(
        "mma.sync.aligned.m16n8k16.row.col.f32.bf16.bf16.f32 "
        "{%0,%1,%2,%3}, {%4,%5,%6,%7}, {%8,%9}, {%0,%1,%2,%3};"
        : "+f"(c[0]), "+f"(c[1]), "+f"(c[2]), "+f"(c[3])
        : "r"(a[0]), "r"(a[1]), "r"(a[2]), "r"(a[3]), "r"(b0), "r"(b1));
}

// ---------------------------------------------------------------------------
// prep: W fp32 -> bf16 hi/lo packed pairs (flat pair index = g*32 + k/2)
// ---------------------------------------------------------------------------
__global__ void prep_w_kernel(const float* __restrict__ Wm) {
    int i = blockIdx.x * 256 + threadIdx.x;          // 16384 pairs
    float a = Wm[2 * i], b = Wm[2 * i + 1];
    g_wh[i] = pack_bf16_hi(a, b);
    g_wl[i] = pack_bf16_lo(a, b);
}

// ---------------------------------------------------------------------------
// HMMA GEMM: pre[m][n] = sum_k x[m][k] * W[n][k].  CTA: M=64, N=512, K=64.
// 8 warps: warp w -> m rows [(w>>2)*32, +32), n cols [(w&3)*128, +128).
// smem rows padded to 72 bf16 (36 uints) -> conflict-free fragment LDS.
// ---------------------------------------------------------------------------
#define ARS 36                     // A/B smem row stride in uints (72 bf16)
#define OFF_AH 0
#define OFF_AL (64 * ARS)
#define OFF_BH (2 * 64 * ARS)
#define OFF_BL (OFF_BH + 512 * ARS)
#define GEMM_SMEM_UINTS (OFF_BL + 512 * ARS)
#define GEMM_SMEM_BYTES (GEMM_SMEM_UINTS * 4)

__global__ void __launch_bounds__(256, 1)
pre_gemm_mma(const float* __restrict__ xg, float* __restrict__ pre)
{
    extern __shared__ unsigned usm[];
    unsigned* Ah = usm + OFF_AH;
    unsigned* Al = usm + OFF_AL;
    unsigned* Bh = usm + OFF_BH;
    unsigned* Bl = usm + OFF_BL;

    const int tid = threadIdx.x;

    // ---- A tile: 64 rows x 64 k fp32 -> bf16 hi/lo ----
    {
        const float* xt = xg + (long long)blockIdx.x * 64 * II;
#pragma unroll
        for (int j = 0; j < 8; j++) {
            int idx = tid + j * 256;                 // float2 index, 2048 total
            int row = idx >> 5, kp = idx & 31;
            float2 v = *(const float2*)(xt + row * II + kp * 2);
            Ah[row * ARS + kp] = pack_bf16_hi(v.x, v.y);
            Al[row * ARS + kp] = pack_bf16_lo(v.x, v.y);
        }
    }
    // ---- B tile: full W 512 x 64 from prepped buffers (uint4) ----
    {
#pragma unroll
        for (int j = 0; j < 16; j++) {
            int idx = tid + j * 256;                 // uint4 index, 4096 total
            int n = idx >> 3, kq = idx & 7;
            uint4 hv = ((const uint4*)g_wh)[idx];
            uint4 lv = ((const uint4*)g_wl)[idx];
            *(uint4*)(Bh + n * ARS + kq * 4) = hv;
            *(uint4*)(Bl + n * ARS + kq * 4) = lv;
        }
    }
    __syncthreads();

    const int w    = tid >> 5;
    const int lane = tid & 31;
    const int gid  = lane >> 2;        // groupID
    const int tig  = lane & 3;         // thread-in-group
    const int mg   = w >> 2;           // m group (0..1)
    const int ng   = w & 3;            // n group (0..3)

    float acc[2][16][4];
#pragma unroll
    for (int mt = 0; mt < 2; mt++)
#pragma unroll
        for (int nc = 0; nc < 16; nc++)
#pragma unroll
            for (int e = 0; e < 4; e++) acc[mt][nc][e] = 0.0f;

#pragma unroll
    for (int ks = 0; ks < 4; ks++) {
        unsigned ah[2][4], al[2][4];
#pragma unroll
        for (int mt = 0; mt < 2; mt++) {
            int r0 = mg * 32 + mt * 16 + gid;
            int ui = ks * 8 + tig;
            ah[mt][0] = Ah[r0 * ARS + ui];
            ah[mt][1] = Ah[(r0 + 8) * ARS + ui];
            ah[mt][2] = Ah[r0 * ARS + ui + 4];
            ah[mt][3] = Ah[(r0 + 8) * ARS + ui + 4];
            al[mt][0] = Al[r0 * ARS + ui];
            al[mt][1] = Al[(r0 + 8) * ARS + ui];
            al[mt][2] = Al[r0 * ARS + ui + 4];
            al[mt][3] = Al[(r0 + 8) * ARS + ui + 4];
        }
#pragma unroll
        for (int nc = 0; nc < 16; nc++) {
            int n  = ng * 128 + nc * 8 + gid;
            int ui = ks * 8 + tig;
            unsigned bh0 = Bh[n * ARS + ui];
            unsigned bh1 = Bh[n * ARS + ui + 4];
            unsigned bl0 = Bl[n * ARS + ui];
            unsigned bl1 = Bl[n * ARS + ui + 4];
#pragma unroll
            for (int mt = 0; mt < 2; mt++) {
                mma16816(acc[mt][nc], ah[mt], bh0, bh1);   // xh*wh
                mma16816(acc[mt][nc], al[mt], bh0, bh1);   // xl*wh
                mma16816(acc[mt][nc], ah[mt], bl0, bl1);   // xh*wl
            }
        }
    }

    // ---- store ----
#pragma unroll
    for (int mt = 0; mt < 2; mt++) {
#pragma unroll
        for (int nc = 0; nc < 16; nc++) {
            long long m = (long long)blockIdx.x * 64 + mg * 32 + mt * 16 + gid;
            int n = ng * 128 + nc * 8 + tig * 2;
            *(float2*)(pre + m * GG + n)       = make_float2(acc[mt][nc][0], acc[mt][nc][1]);
            *(float2*)(pre + (m + 8) * GG + n) = make_float2(acc[mt][nc][2], acc[mt][nc][3]);
        }
    }
}

// ---------------------------------------------------------------------------
// scan: pure-packed mainloop (96 reg rows + 32 smem rows), shuffle epilogue.
// Lane l of warp w owns cols c0 = 16l + 2w, c1 = c0 + 1.
// ---------------------------------------------------------------------------
__global__ void __launch_bounds__(NTHR, 1)
slstm_scan_kernel(const float* __restrict__ pre, const float* __restrict__ Rm,
                  const float* __restrict__ bias, float* __restrict__ out)
{
    extern __shared__ float smem[];
    float* sW = smem;                    // [NTHR][PTS]
    float* hb = smem + SW_FLOATS;        // [2][2][HH]

    const int tid = threadIdx.x;
    const int w   = tid >> 5;
    const int l   = tid & 31;
    const int c0  = 16 * l + 2 * w;
    const int c1  = c0 + 1;
    const int b0  = blockIdx.x * 2;

    u64 wp0[REG_K / 2], wp1[REG_K / 2];
#pragma unroll
    for (int j = 0; j < REG_K / 2; j++) {
        wp0[j] = packf2(Rm[(2 * j) * GG + c0], Rm[(2 * j + 1) * GG + c0]);
        wp1[j] = packf2(Rm[(2 * j) * GG + c1], Rm[(2 * j + 1) * GG + c1]);
    }
    {
        float* slab = sW + tid * PTS;
#pragma unroll
        for (int kc = 0; kc < SMK; kc += 4) {
            int k = REG_K + kc;
            slab[kc * 2 + 0] = Rm[(k + 0) * GG + c0];
            slab[kc * 2 + 1] = Rm[(k + 1) * GG + c0];
            slab[kc * 2 + 2] = Rm[(k + 0) * GG + c1];
            slab[kc * 2 + 3] = Rm[(k + 1) * GG + c1];
            slab[kc * 2 + 4] = Rm[(k + 2) * GG + c0];
            slab[kc * 2 + 5] = Rm[(k + 3) * GG + c0];
            slab[kc * 2 + 6] = Rm[(k + 2) * GG + c1];
            slab[kc * 2 + 7] = Rm[(k + 3) * GG + c1];
        }
    }
    const float bg0 = bias[c0];
    const float bg1 = bias[c1];

    hb[tid] = 0.0f;
    hb[tid + 256] = 0.0f;
    __syncthreads();

    const float* pr0 = pre + (long long)(b0)     * SS * GG;
    const float* pr1 = pre + (long long)(b0 + 1) * SS * GG;

    float2 p0 = __ldg((const float2*)(pr0 + c0));
    float2 p1 = __ldg((const float2*)(pr1 + c0));

    const int my_row = (l >> 4) & 1;
    const int my_hid = 16 * (l & 7) + 2 * w + ((l >> 3) & 1);
    float c_ = 0.0f, n_ = 0.0f, m_ = 0.0f;

    const bool lo16 = (l < 16);
    const bool b3   = ((l >> 3) & 1) != 0;
    const float* sWg = sW + tid * PTS;

#pragma unroll 1
    for (int step = 0; step < SS; step++) {
        const float* h0 = hb + (step & 1) * 256;
        const float* h1 = h0 + HH;
        float* hn = hb + ((step + 1) & 1) * 256;

        float2 q0 = make_float2(0.f, 0.f), q1 = make_float2(0.f, 0.f);
        if (step + 1 < SS) {
            long long off = (long long)(step + 1) * GG;
            q0 = __ldg((const float2*)(pr0 + off + c0));
            q1 = __ldg((const float2*)(pr1 + off + c0));
        }

        u64 a00 = 0, a10 = 0, a01 = 0, a11 = 0;   // a{col}{row}

#pragma unroll
        for (int k = 0; k < REG_K; k += 4) {
            ulonglong2 hp0 = *(const ulonglong2*)(h0 + k);
            ulonglong2 hp1 = *(const ulonglong2*)(h1 + k);
            int j = k / 2;
            a00 = ffma2(hp0.x, wp0[j],     a00);
            a10 = ffma2(hp0.x, wp1[j],     a10);
            a01 = ffma2(hp1.x, wp0[j],     a01);
            a11 = ffma2(hp1.x, wp1[j],     a11);
            a00 = ffma2(hp0.y, wp0[j + 1], a00);
            a10 = ffma2(hp0.y, wp1[j + 1], a10);
            a01 = ffma2(hp1.y, wp0[j + 1], a01);
            a11 = ffma2(hp1.y, wp1[j + 1], a11);
        }
#pragma unroll
        for (int k = 0; k < SMK; k += 4) {
            ulonglong2 wv0 = *(const ulonglong2*)(sWg + k * 2);
            ulonglong2 wv1 = *(const ulonglong2*)(sWg + k * 2 + 4);
            ulonglong2 hp0 = *(const ulonglong2*)(h0 + REG_K + k);
            ulonglong2 hp1 = *(const ulonglong2*)(h1 + REG_K + k);
            a00 = ffma2(hp0.x, wv0.x, a00);
            a10 = ffma2(hp0.x, wv0.y, a10);
            a01 = ffma2(hp1.x, wv0.x, a01);
            a11 = ffma2(hp1.x, wv0.y, a11);
            a00 = ffma2(hp0.y, wv1.x, a00);
            a10 = ffma2(hp0.y, wv1.y, a10);
            a01 = ffma2(hp1.y, wv1.x, a01);
            a11 = ffma2(hp1.y, wv1.y, a11);
        }

        float2 t0 = unpackf2(a00), t1 = unpackf2(a10);
        float2 t2 = unpackf2(a01), t3 = unpackf2(a11);
        float aa = t0.x + t0.y + p0.x + bg0;   // g(r0, c0)
        float bb = t1.x + t1.y + p0.y + bg1;   // g(r0, c1)
        float cc = t2.x + t2.y + p1.x + bg0;   // g(r1, c0)
        float dd = t3.x + t3.y + p1.y + bg1;   // g(r1, c1)

        // warp-local gate transpose (4 shuffles)
        float u1 = lo16 ? cc : aa;
        float u2 = lo16 ? dd : bb;
        float r1v = __shfl_xor_sync(0xFFFFFFFFu, u1, 16);
        float r2v = __shfl_xor_sync(0xFFFFFFFFu, u2, 16);
        float A = lo16 ? aa : r1v;
        float B = lo16 ? bb : r2v;
        float C = lo16 ? r1v : cc;
        float D = lo16 ? r2v : dd;
        float s1in = b3 ? A : B;
        float s2in = b3 ? C : D;
        float e1 = __shfl_xor_sync(0xFFFFFFFFu, s1in, 8);
        float e2 = __shfl_xor_sync(0xFFFFFFFFu, s2in, 8);
        float iv = b3 ? e1 : A;
        float fv = b3 ? B  : e1;
        float ov = b3 ? e2 : C;
        float zv = b3 ? D  : e2;

        float tz = fast_tanh(zv);
        float so = __fdividef(1.0f, 1.0f + __expf(-ov));
        float lf = fminf(fv, 0.0f) - __logf(1.0f + __expf(-fabsf(fv)));
        float mn = fmaxf(lf + m_, iv);
        float ip = __expf(iv - mn);
        float fp = __expf(lf + m_ - mn);
        c_ = fp * c_ + ip * tz;
        n_ = fp * n_ + ip;
        m_ = mn;
        float hv = so * fast_tanh(__fdividef(c_, n_));

        hn[my_row * HH + my_hid] = hv;
        out[((long long)(b0 + my_row) * SS + step) * HH + my_hid] = hv;

        p0 = q0; p1 = q1;
        __syncthreads();
    }
}

extern "C" void kernel_launch(void* const* d_in, const int* in_sizes, int n_in,
                              void* d_out, int out_size)
{
    const float* xg = (const float*)d_in[0];
    const float* Wm = (const float*)d_in[1];
    const float* Rm = (const float*)d_in[2];
    const float* bv = (const float*)d_in[3];
    if (n_in >= 3 && in_sizes[1] == HH * GG && in_sizes[2] == GG * II) {
        const float* t = Wm; Wm = Rm; Rm = t;
    }
    float* out = (float*)d_out;

    float* pre = nullptr;
    cudaGetSymbolAddress((void**)&pre, g_pre);

    cudaFuncSetAttribute(pre_gemm_mma,
                         cudaFuncAttributeMaxDynamicSharedMemorySize, GEMM_SMEM_BYTES);
    cudaFuncSetAttribute(slstm_scan_kernel,
                         cudaFuncAttributeMaxDynamicSharedMemorySize, SCAN_SMEM_BYTES);

    prep_w_kernel<<<GG * II / 2 / 256, 256>>>(Wm);
    pre_gemm_mma<<<(BB * SS) / 64, 256, GEMM_SMEM_BYTES>>>(xg, pre);
    slstm_scan_kernel<<<NCTA, NTHR, SCAN_SMEM_BYTES>>>(pre, Rm, bv, out);
}